// round 15
// baseline (speedup 1.0000x reference)
#include <cuda_runtime.h>
#include <cuda_fp16.h>
#include <math.h>
#include <stdint.h>

// ---------------- problem constants ----------------
#define B_    2
#define S_    2048
#define DIM_  2048
#define NH_   16
#define HD_   128
#define HID_  5632
#define M_    (B_*S_)
#define EPS_  1e-5f
#define SCALE_ 0.08838834764831845f   // 1/sqrt(128)

// ---------------- scratch (device globals; no allocation) ----------------
__device__ __half g_h   [(size_t)M_*DIM_];
__device__ __half g_qkv [(size_t)M_*2*DIM_];          // [m][q|k]  (row stride 2*DIM)
__device__ __half g_vt  [(size_t)NH_*HD_*M_];         // [h*128+d][b*S+s]
__device__ __half g_att [(size_t)M_*DIM_];
__device__ float  g_h1  [(size_t)M_*DIM_];
__device__ __half g_f   [(size_t)M_*DIM_];
__device__ __half g_ff  [(size_t)M_*HID_];
__device__ __half g_bm16[(size_t)NH_*S_*S_];          // half(bias + mask)
// fp16 weight copies
__device__ __half g_wqkv[(size_t)3*DIM_*DIM_];        // wq | wk | wv
__device__ __half g_wo  [(size_t)DIM_*DIM_];
__device__ __half g_w13 [(size_t)2*HID_*DIM_];        // interleaved rows: 2j=w1[j], 2j+1=w3[j]
__device__ __half g_w2  [(size_t)DIM_*HID_];

// ---------------- helpers ----------------
__device__ __forceinline__ uint32_t smem_u32(const void* p){
    uint32_t a;
    asm("{ .reg .u64 t; cvta.to.shared.u64 t, %1; cvt.u32.u64 %0, t; }" : "=r"(a) : "l"(p));
    return a;
}
__device__ __forceinline__ uint32_t swz(uint32_t x){ return x ^ ((x >> 3) & 0x70); }
#define CP16(dst, src) asm volatile("cp.async.cg.shared.global [%0], [%1], 16;" :: "r"(dst), "l"(src))

__device__ __forceinline__ void ldsm4(uint32_t* r, uint32_t addr){
    asm volatile("ldmatrix.sync.aligned.m8n8.x4.shared.b16 {%0,%1,%2,%3}, [%4];"
        : "=r"(r[0]),"=r"(r[1]),"=r"(r[2]),"=r"(r[3]) : "r"(addr));
}
__device__ __forceinline__ void mma16816(float* c, const uint32_t* a, const uint32_t* b){
    asm volatile("mma.sync.aligned.m16n8k16.row.col.f32.f16.f16.f32 "
        "{%0,%1,%2,%3}, {%4,%5,%6,%7}, {%8,%9}, {%0,%1,%2,%3};"
        : "+f"(c[0]),"+f"(c[1]),"+f"(c[2]),"+f"(c[3])
        : "r"(a[0]),"r"(a[1]),"r"(a[2]),"r"(a[3]), "r"(b[0]),"r"(b[1]));
}
__device__ __forceinline__ uint32_t pack2h(float a, float b){
    __half2 h = __floats2half2_rn(a, b);
    return *reinterpret_cast<uint32_t*>(&h);
}

// =====================================================================
// fp16 mma.sync GEMM: C[m,n] (+epi) = sum_k A[m,k]*B[n,k]
// CTA 128 x 128, BK=64 (128B rows, SW128), 3-stage cp.async, 2 CTAs/SM.
// epi: 1 half-out, 2 fp32-out + residual Rb, 4 swiglu-interleaved (N/2 cols),
//      5 half-out with SCALE_ on cols < DIM_ (q part of qk GEMM)
// =====================================================================
#define NSTAGE 3
#define BN_ 128

__global__ __launch_bounds__(256, 2) void mm_h(
    const __half* __restrict__ A, const __half* __restrict__ B, void* __restrict__ Cv,
    const float* __restrict__ Rb,
    int K, int lda, int ldb, int ldc, int epi)
{
    constexpr int WN = BN_ / 4;       // 32
    constexpr int NF = WN / 8;        // 4
    constexpr int STAGE = (128 + BN_) * 128;   // 32768 B
    constexpr int BI = BN_ / 32;      // 4

    extern __shared__ char smem[];
    const uint32_t sbase = (smem_u32(smem) + 127u) & ~127u;

    const int tid = threadIdx.x;
    const int wid = tid >> 5, lane = tid & 31;
    const int wm = (wid >> 2) * 64;
    const int wn = (wid & 3) * WN;
    const int bm = blockIdx.y * 128, bn = blockIdx.x * BN_;

    const int tA = lane >> 3;
    const int rA = (tA & 1) * 8 + (lane & 7);
    const int cA = tA >> 1;
    const int rB = (tA >> 1) * 8 + (lane & 7);
    const int cB = tA & 1;

    float acc[4][NF][4];
    #pragma unroll
    for (int i = 0; i < 4; i++)
        #pragma unroll
        for (int j = 0; j < NF; j++)
            { acc[i][j][0]=0.f; acc[i][j][1]=0.f; acc[i][j][2]=0.f; acc[i][j][3]=0.f; }

    const int nch = K >> 6;

    auto produce = [&](int c) {
        const uint32_t sA = sbase + (c % NSTAGE) * STAGE;
        const uint32_t sB = sA + 128 * 128;
        const int k0 = c << 6;
        #pragma unroll
        for (int i = 0; i < 4; i++) {
            int idx = tid + 256 * i; int row = idx >> 3, seg = idx & 7;
            CP16(sA + swz(row * 128 + seg * 16),
                 A + (size_t)(bm + row) * lda + k0 + seg * 8);
        }
        #pragma unroll
        for (int i = 0; i < BI; i++) {
            int idx = tid + 256 * i; int row = idx >> 3, seg = idx & 7;
            CP16(sB + swz(row * 128 + seg * 16),
                 B + (size_t)(bn + row) * ldb + k0 + seg * 8);
        }
        asm volatile("cp.async.commit_group;" ::: "memory");
    };

    produce(0);
    if (nch > 1) produce(1);

    for (int c = 0; c < nch; c++) {
        if (c < nch - 1) asm volatile("cp.async.wait_group 1;" ::: "memory");
        else             asm volatile("cp.async.wait_group 0;" ::: "memory");
        __syncthreads();
        if (c + 2 < nch) produce(c + 2);

        const uint32_t sA = sbase + (c % NSTAGE) * STAGE;
        const uint32_t sB = sA + 128 * 128;
        #pragma unroll
        for (int kk = 0; kk < 4; kk++) {
            uint32_t a[4][4];
            #pragma unroll
            for (int mf = 0; mf < 4; mf++) {
                const int row = wm + mf * 16 + rA;
                ldsm4(a[mf], sA + row * 128 + (((cA + 2*kk) ^ (rA & 7)) * 16));
            }
            uint32_t b[NF][2];
            #pragma unroll
            for (int nf2 = 0; nf2 < NF/2; nf2++) {
                uint32_t t[4];
                const int row = wn + nf2 * 16 + rB;
                ldsm4(t, sB + row * 128 + (((cB + 2*kk) ^ (rB & 7)) * 16));
                b[2*nf2][0]=t[0]; b[2*nf2][1]=t[1];
                b[2*nf2+1][0]=t[2]; b[2*nf2+1][1]=t[3];
            }
            #pragma unroll
            for (int mf = 0; mf < 4; mf++)
                #pragma unroll
                for (int nf = 0; nf < NF; nf++)
                    mma16816(acc[mf][nf], a[mf], b[nf]);
        }
    }
    __syncthreads();

    #pragma unroll
    for (int mf = 0; mf < 4; mf++) {
        const int r0 = bm + wm + mf * 16 + (lane >> 2);
        const int r1 = r0 + 8;
        #pragma unroll
        for (int nf = 0; nf < NF; nf++) {
            const int col = bn + wn + nf * 8 + (lane & 3) * 2;
            float2 v0 = make_float2(acc[mf][nf][0], acc[mf][nf][1]);
            float2 v1 = make_float2(acc[mf][nf][2], acc[mf][nf][3]);
            if (epi == 4) {
                __half* C = (__half*)Cv;
                float a0 = v0.x / (1.0f + __expf(-v0.x)) * v0.y;
                float a1 = v1.x / (1.0f + __expf(-v1.x)) * v1.y;
                C[(size_t)r0 * ldc + (col >> 1)] = __float2half_rn(a0);
                C[(size_t)r1 * ldc + (col >> 1)] = __float2half_rn(a1);
            } else if (epi == 1) {
                __half* C = (__half*)Cv;
                *(uint32_t*)(C + (size_t)r0 * ldc + col) = pack2h(v0.x, v0.y);
                *(uint32_t*)(C + (size_t)r1 * ldc + col) = pack2h(v1.x, v1.y);
            } else if (epi == 5) {
                __half* C = (__half*)Cv;
                const float sc = (col < DIM_) ? SCALE_ : 1.0f;
                *(uint32_t*)(C + (size_t)r0 * ldc + col) = pack2h(v0.x*sc, v0.y*sc);
                *(uint32_t*)(C + (size_t)r1 * ldc + col) = pack2h(v1.x*sc, v1.y*sc);
            } else {
                float* C = (float*)Cv;
                float2 a0 = *(const float2*)(Rb + (size_t)r0 * ldc + col);
                float2 a1 = *(const float2*)(Rb + (size_t)r1 * ldc + col);
                v0.x += a0.x; v0.y += a0.y;
                v1.x += a1.x; v1.y += a1.y;
                *(float2*)(C + (size_t)r0 * ldc + col) = v0;
                *(float2*)(C + (size_t)r1 * ldc + col) = v1;
            }
        }
    }
}

// =====================================================================
// Flash attention (fp16 in, fp32 softmax/accum). Q pre-scaled by 1/sqrt(d).
// No online max; P -> A-fragments directly in registers (no P smem).
// TRIPLE-buffered K/V: the Q smem region (dead after qf load) is recycled as
// the third buffer. buf i lives in region (i+1)%3; K@+0 (pitch 272),
// V@+17408 (pitch 144), region stride 35840. No trailing barrier per tile;
// loadKV(kt+2) issues right after the top barrier, overlapping compute.
// =====================================================================
#define FL_REG  35840
#define FL_SMEM (3*FL_REG + 128)     // 107648 -> still 2 CTAs/SM

__global__ __launch_bounds__(256, 2) void flash_k()
{
    extern __shared__ char smem[];
    const uint32_t sb = (smem_u32(smem) + 127u) & ~127u;

    const int tid = threadIdx.x;
    const int w = tid >> 5, lane = tid & 31;
    const int tA = lane >> 3;
    const int rA = (tA & 1) * 8 + (lane & 7);
    const int cA = tA >> 1;
    const int rB = (tA >> 1) * 8 + (lane & 7);
    const int cB = tA & 1;

    const int z = blockIdx.y, b = z >> 4, h = z & 15;
    const int bm = blockIdx.x * 128;

    const __half* qbase = g_qkv + (size_t)(b*S_ + bm) * (2*DIM_) + h*HD_;
    const __half* kbase = g_qkv + (size_t)(b*S_) * (2*DIM_) + DIM_ + h*HD_;
    const __half* vbase = g_vt + (size_t)h * HD_ * M_ + b*S_;   // row stride M_
    const __half* bmb   = g_bm16 + (size_t)h * S_ * S_;

    // buf i -> region (i+1)%3
    auto loadKV = [&](int kt) {
        const uint32_t reg = sb + (uint32_t)(((kt % 3) + 1) % 3) * FL_REG;
        const uint32_t ok = reg;
        const uint32_t ov = reg + 17408;
        #pragma unroll
        for (int i = 0; i < 4; i++) {       // K: 64 rows x 16 segs
            int idx = tid + 256*i; int r = idx >> 4, sg = idx & 15;
            CP16(ok + r*272 + sg*16, kbase + (size_t)(kt*64 + r) * (2*DIM_) + sg*8);
        }
        #pragma unroll
        for (int i = 0; i < 4; i++) {       // V: 128 d-rows x 8 segs
            int idx = tid + 256*i; int r = idx >> 3, sg = idx & 7;
            CP16(ov + r*144 + sg*16, vbase + (size_t)r * M_ + kt*64 + sg*8);
        }
        asm volatile("cp.async.commit_group;" ::: "memory");
    };

    // Q tile -> region 0 (128 rows x 16 segs, pitch 272); reused as buf2 later
    #pragma unroll
    for (int i = 0; i < 8; i++) {
        int idx = tid + 256*i; int r = idx >> 4, sg = idx & 15;
        CP16(sb + r*272 + sg*16, qbase + (size_t)r * (2*DIM_) + sg*8);
    }
    asm volatile("cp.async.commit_group;" ::: "memory");
    loadKV(0);    // region 1
    loadKV(1);    // region 2
    asm volatile("cp.async.wait_group 0;" ::: "memory");
    __syncthreads();

    uint32_t qf[8][4];
    #pragma unroll
    for (int kb = 0; kb < 8; kb++)
        ldsm4(qf[kb], sb + (w*16 + rA)*272 + (cA + 2*kb)*16);
    __syncthreads();   // all warps hold qf; region 0 now free for buf2

    const int gr0 = bm + w*16 + (lane >> 2);
    const int gr1 = gr0 + 8;
    const __half2* bm0 = (const __half2*)(bmb + (size_t)gr0*S_ + (lane & 3)*2);
    const __half2* bm1 = (const __half2*)(bmb + (size_t)gr1*S_ + (lane & 3)*2);

    float l0 = 0.f, l1 = 0.f;
    float oacc[16][4];
    #pragma unroll
    for (int i = 0; i < 16; i++)
        { oacc[i][0]=0.f; oacc[i][1]=0.f; oacc[i][2]=0.f; oacc[i][3]=0.f; }

    for (int kt = 0; kt < 32; kt++) {
        // ---- prefetch bm16 tile into registers (latency hidden by S-MMA) ----
        uint32_t bmv0[8], bmv1[8];
        #pragma unroll
        for (int nf = 0; nf < 8; nf++) {
            bmv0[nf] = *(const uint32_t*)(bm0 + (kt*32 + nf*4));
            bmv1[nf] = *(const uint32_t*)(bm1 + (kt*32 + nf*4));
        }

        if (kt < 31) asm volatile("cp.async.wait_group 1;" ::: "memory");
        else         asm volatile("cp.async.wait_group 0;" ::: "memory");
        __syncthreads();
        // issue next-next tile immediately: writes region kt%3, which all warps
        // finished reading in iteration kt-1 (guaranteed by the barrier above)
        if (kt + 2 < 32) loadKV(kt + 2);

        const uint32_t reg = sb + (uint32_t)(((kt % 3) + 1) % 3) * FL_REG;
        const uint32_t ok = reg;
        const uint32_t ov = reg + 17408;

        // ---- S = Q @ K^T ----
        float sacc[8][4];
        #pragma unroll
        for (int i = 0; i < 8; i++)
            { sacc[i][0]=0.f; sacc[i][1]=0.f; sacc[i][2]=0.f; sacc[i][3]=0.f; }
        #pragma unroll
        for (int kb = 0; kb < 8; kb++) {
            #pragma unroll
            for (int nf2 = 0; nf2 < 4; nf2++) {
                uint32_t t[4];
                ldsm4(t, ok + (nf2*16 + rB)*272 + (cB + 2*kb)*16);
                uint32_t b0[2] = {t[0], t[1]}, b1[2] = {t[2], t[3]};
                mma16816(sacc[2*nf2],   qf[kb], b0);
                mma16816(sacc[2*nf2+1], qf[kb], b1);
            }
        }

        // ---- p = exp(s + bias+mask), pack directly into A-fragments ----
        float rs0 = 0.f, rs1 = 0.f;
        uint32_t pa[4][4];
        #pragma unroll
        for (int nf = 0; nf < 8; nf++) {
            float2 f0 = __half22float2(*(const __half2*)&bmv0[nf]);
            float2 f1 = __half22float2(*(const __half2*)&bmv1[nf]);
            float p0 = __expf(sacc[nf][0] + f0.x);
            float p1 = __expf(sacc[nf][1] + f0.y);
            float p2 = __expf(sacc[nf][2] + f1.x);
            float p3 = __expf(sacc[nf][3] + f1.y);
            rs0 += p0 + p1;
            rs1 += p2 + p3;
            pa[nf >> 1][(nf & 1) * 2]     = pack2h(p0, p1);
            pa[nf >> 1][(nf & 1) * 2 + 1] = pack2h(p2, p3);
        }
        l0 += rs0;
        l1 += rs1;

        // ---- O += P @ V (P consumed straight from registers) ----
        #pragma unroll
        for (int kb = 0; kb < 4; kb++) {
            #pragma unroll
            for (int nf2 = 0; nf2 < 8; nf2++) {
                uint32_t t[4];
                ldsm4(t, ov + (nf2*16 + rB)*144 + (cB + 2*kb)*16);
                uint32_t b0[2] = {t[0], t[1]}, b1[2] = {t[2], t[3]};
                mma16816(oacc[2*nf2],   pa[kb], b0);
                mma16816(oacc[2*nf2+1], pa[kb], b1);
            }
        }
        // no trailing barrier: triple buffering makes the next write safe
    }

    // reduce l over the quad (lanes sharing a row)
    l0 += __shfl_xor_sync(0xffffffffu, l0, 1);
    l0 += __shfl_xor_sync(0xffffffffu, l0, 2);
    l1 += __shfl_xor_sync(0xffffffffu, l1, 1);
    l1 += __shfl_xor_sync(0xffffffffu, l1, 2);

    const float inv0 = 1.0f / l0, inv1 = 1.0f / l1;
    __half* o0 = g_att + (size_t)(b*S_ + gr0) * DIM_ + h*HD_;
    __half* o1 = g_att + (size_t)(b*S_ + gr1) * DIM_ + h*HD_;
    #pragma unroll
    for (int nfd = 0; nfd < 16; nfd++) {
        const int dc = nfd*8 + (lane & 3)*2;
        *(uint32_t*)(o0 + dc) = pack2h(oacc[nfd][0]*inv0, oacc[nfd][1]*inv0);
        *(uint32_t*)(o1 + dc) = pack2h(oacc[nfd][2]*inv1, oacc[nfd][3]*inv1);
    }
}

// ---------------- weight copy fp32 -> fp16 ----------------
__global__ __launch_bounds__(256) void cvt_h(const float* __restrict__ src,
                                             __half* __restrict__ dst, size_t n4)
{
    const size_t stride = (size_t)gridDim.x * 256;
    for (size_t i = (size_t)blockIdx.x * 256 + threadIdx.x; i < n4; i += stride) {
        float4 v = *(const float4*)(src + i * 4);
        __half2* d2 = (__half2*)(dst + i * 4);
        d2[0] = __floats2half2_rn(v.x, v.y);
        d2[1] = __floats2half2_rn(v.z, v.w);
    }
}

// ---------------- bm16 = half(bias + mask) ----------------
__global__ __launch_bounds__(256) void prep_bm(const float* __restrict__ bias,
                                               const float* __restrict__ mask,
                                               __half* __restrict__ dst)
{
    const size_t n4 = (size_t)NH_*S_*S_/4;
    const size_t stride = (size_t)gridDim.x * 256;
    for (size_t i = (size_t)blockIdx.x * 256 + threadIdx.x; i < n4; i += stride) {
        float4 bv = ((const float4*)bias)[i];
        float4 mv = ((const float4*)mask)[i & ((size_t)S_*S_/4 - 1)];
        __half2* d2 = (__half2*)(dst + i * 4);
        d2[0] = __floats2half2_rn(bv.x + mv.x, bv.y + mv.y);
        d2[1] = __floats2half2_rn(bv.z + mv.z, bv.w + mv.w);
    }
}

// ---------------- interleave w1/w3 rows -> fp16 ----------------
__global__ __launch_bounds__(256) void ilv_w13(const float* __restrict__ w1,
                                               const float* __restrict__ w3,
                                               __half* __restrict__ dst)
{
    const size_t idx = (size_t)blockIdx.x * 256 + threadIdx.x;   // 2*HID*512
    const size_t rr = idx >> 9, sg = idx & 511;
    const float* src = (rr & 1) ? w3 : w1;
    float4 v = *(const float4*)(src + (rr >> 1) * DIM_ + sg * 4);
    __half2* d2 = (__half2*)(dst + rr * DIM_ + sg * 4);
    d2[0] = __floats2half2_rn(v.x, v.y);
    d2[1] = __floats2half2_rn(v.z, v.w);
}

// ---------------- rmsnorm: fp32 in -> fp16 out ----------------
__global__ __launch_bounds__(256) void rmsnorm_k(const float* __restrict__ x,
                                                 const float* __restrict__ w,
                                                 __half* __restrict__ o)
{
    __shared__ float red[8];
    const size_t row = blockIdx.x;
    const float* xr = x + row * (size_t)DIM_;
    const int tid = threadIdx.x;
    float4 v0 = *(const float4*)(xr + tid*4);
    float4 v1 = *(const float4*)(xr + 1024 + tid*4);
    float s = v0.x*v0.x + v0.y*v0.y + v0.z*v0.z + v0.w*v0.w
            + v1.x*v1.x + v1.y*v1.y + v1.z*v1.z + v1.w*v1.w;
    #pragma unroll
    for (int off = 16; off > 0; off >>= 1) s += __shfl_xor_sync(0xffffffffu, s, off);
    if ((tid & 31) == 0) red[tid >> 5] = s;
    __syncthreads();
    s = red[0]+red[1]+red[2]+red[3]+red[4]+red[5]+red[6]+red[7];
    const float r = rsqrtf(s * (1.0f/DIM_) + EPS_);
    float4 w0 = *(const float4*)(w + tid*4);
    float4 w1 = *(const float4*)(w + 1024 + tid*4);
    __half2* orow = (__half2*)(o + row * (size_t)DIM_);
    orow[tid*2]          = __floats2half2_rn(v0.x*r*w0.x, v0.y*r*w0.y);
    orow[tid*2+1]        = __floats2half2_rn(v0.z*r*w0.z, v0.w*r*w0.w);
    orow[512 + tid*2]    = __floats2half2_rn(v1.x*r*w1.x, v1.y*r*w1.y);
    orow[512 + tid*2+1]  = __floats2half2_rn(v1.z*r*w1.z, v1.w*r*w1.w);
}

// ---------------- launch ----------------
extern "C" void kernel_launch(void* const* d_in, const int* in_sizes, int n_in,
                              void* d_out, int out_size)
{
    (void)in_sizes; (void)n_in; (void)out_size;
    const float* x    = (const float*)d_in[0];
    const float* mask = (const float*)d_in[1];
    const float* bias = (const float*)d_in[2];
    const float* wq   = (const float*)d_in[3];
    const float* wk   = (const float*)d_in[4];
    const float* wv   = (const float*)d_in[5];
    const float* wo   = (const float*)d_in[6];
    const float* w1   = (const float*)d_in[7];
    const float* w2   = (const float*)d_in[8];
    const float* w3   = (const float*)d_in[9];
    const float* anw  = (const float*)d_in[10];
    const float* fnw  = (const float*)d_in[11];
    float* out = (float*)d_out;

    __half *h, *qkv, *vt, *att, *f, *ff, *bm16, *cwqkv, *cwo, *cw13, *cw2;
    float *h1;
    cudaGetSymbolAddress((void**)&h,    g_h);
    cudaGetSymbolAddress((void**)&qkv,  g_qkv);
    cudaGetSymbolAddress((void**)&vt,   g_vt);
    cudaGetSymbolAddress((void**)&att,  g_att);
    cudaGetSymbolAddress((void**)&h1,   g_h1);
    cudaGetSymbolAddress((void**)&f,    g_f);
    cudaGetSymbolAddress((void**)&ff,   g_ff);
    cudaGetSymbolAddress((void**)&bm16, g_bm16);
    cudaGetSymbolAddress((void**)&cwqkv,g_wqkv);
    cudaGetSymbolAddress((void**)&cwo,  g_wo);
    cudaGetSymbolAddress((void**)&cw13, g_w13);
    cudaGetSymbolAddress((void**)&cw2,  g_w2);

    const int SMH = NSTAGE * (128 + BN_) * 128 + 256;   // ~96.3 KB -> 2 CTAs/SM
    cudaFuncSetAttribute(mm_h, cudaFuncAttributeMaxDynamicSharedMemorySize, SMH);
    cudaFuncSetAttribute(flash_k, cudaFuncAttributeMaxDynamicSharedMemorySize, FL_SMEM);

    // ---- ONE side stream (R9-proven memory footprint; objects intentionally
    //      not destroyed: destroying mid-capture would invalidate the graph) ----
    cudaStream_t s1;
    cudaStreamCreate(&s1);
    cudaEvent_t eF, eQK, eV, eBM, eWo, eW13, eW2;
    cudaEventCreateWithFlags(&eF,   cudaEventDisableTiming);
    cudaEventCreateWithFlags(&eQK,  cudaEventDisableTiming);
    cudaEventCreateWithFlags(&eV,   cudaEventDisableTiming);
    cudaEventCreateWithFlags(&eBM,  cudaEventDisableTiming);
    cudaEventCreateWithFlags(&eWo,  cudaEventDisableTiming);
    cudaEventCreateWithFlags(&eW13, cudaEventDisableTiming);
    cudaEventCreateWithFlags(&eW2,  cudaEventDisableTiming);

    cudaEventRecord(eF, 0);
    cudaStreamWaitEvent(s1, eF, 0);

    cvt_h<<<1024, 256, 0, s1>>>(wq, cwqkv,                       (size_t)DIM_*DIM_/4);
    cvt_h<<<1024, 256, 0, s1>>>(wk, cwqkv + (size_t)DIM_*DIM_,   (size_t)DIM_*DIM_/4);
    cudaEventRecord(eQK, s1);
    cvt_h<<<1024, 256, 0, s1>>>(wv, cwqkv + (size_t)2*DIM_*DIM_, (size_t)DIM_*DIM_/4);
    cudaEventRecord(eV, s1);
    prep_bm<<<2048, 256, 0, s1>>>(bias, mask, bm16);
    cudaEventRecord(eBM, s1);
    cvt_h<<<1024, 256, 0, s1>>>(wo, cwo,                         (size_t)DIM_*DIM_/4);
    cudaEventRecord(eWo, s1);
    ilv_w13<<<(unsigned)((size_t)2*HID_*512/256), 256, 0, s1>>>(w1, w3, cw13);
    cudaEventRecord(eW13, s1);
    cvt_h<<<1024, 256, 0, s1>>>(w2, cw2,                         (size_t)DIM_*HID_/4);
    cudaEventRecord(eW2, s1);

    // ---- mainline (default stream) — R9 ordering ----
    rmsnorm_k<<<M_, 256>>>(x, anw, h);
    // qk: [M, 4096] = h @ [wq;wk]^T, q cols pre-scaled
    cudaStreamWaitEvent(0, eQK, 0);
    mm_h<<<dim3(2*DIM_/BN_, M_/128), 256, SMH>>>(
        h, cwqkv, qkv, nullptr, DIM_, DIM_, DIM_, 2*DIM_, 5);
    // vt: [2048 d, 4096 tokens] = wv @ h^T (transposed-V GEMM)
    cudaStreamWaitEvent(0, eV, 0);
    mm_h<<<dim3(M_/BN_, DIM_/128), 256, SMH>>>(
        cwqkv + (size_t)2*DIM_*DIM_, h, vt, nullptr, DIM_, DIM_, DIM_, M_, 1);
    cudaStreamWaitEvent(0, eBM, 0);
    flash_k<<<dim3(S_/128, B_*NH_), 256, FL_SMEM>>>();
    cudaStreamWaitEvent(0, eWo, 0);
    mm_h<<<dim3(DIM_/BN_, M_/128), 256, SMH>>>(
        att, cwo, h1, x, DIM_, DIM_, DIM_, DIM_, 2);

    // --- FFN ---
    rmsnorm_k<<<M_, 256>>>(h1, fnw, f);
    cudaStreamWaitEvent(0, eW13, 0);
    mm_h<<<dim3(2*HID_/BN_, M_/128), 256, SMH>>>(
        f, cw13, ff, nullptr, DIM_, DIM_, DIM_, HID_, 4);
    cudaStreamWaitEvent(0, eW2, 0);
    mm_h<<<dim3(DIM_/BN_, M_/128), 256, SMH>>>(
        ff, cw2, out, h1, HID_, HID_, HID_, DIM_, 2);
}

// round 16
// speedup vs baseline: 1.0047x; 1.0047x over previous
#include <cuda_runtime.h>
#include <cuda_fp16.h>
#include <math.h>
#include <stdint.h>

// ---------------- problem constants ----------------
#define B_    2
#define S_    2048
#define DIM_  2048
#define NH_   16
#define HD_   128
#define HID_  5632
#define M_    (B_*S_)
#define EPS_  1e-5f
#define SCALE_ 0.08838834764831845f   // 1/sqrt(128)

// ---------------- scratch (device globals; no allocation) ----------------
__device__ __half g_h   [(size_t)M_*DIM_];
__device__ __half g_qkv [(size_t)M_*2*DIM_];          // [m][q|k]  (row stride 2*DIM)
__device__ __half g_vt  [(size_t)NH_*HD_*M_];         // [h*128+d][b*S+s]
__device__ __half g_att [(size_t)M_*DIM_];
__device__ __half g_h1  [(size_t)M_*DIM_];            // fp16 residual stream
__device__ __half g_f   [(size_t)M_*DIM_];
__device__ __half g_ff  [(size_t)M_*HID_];
__device__ __half g_bm16[(size_t)NH_*S_*S_];          // half(bias + mask)
// fp16 weight copies
__device__ __half g_wqkv[(size_t)3*DIM_*DIM_];        // wq | wk | wv
__device__ __half g_wo  [(size_t)DIM_*DIM_];
__device__ __half g_w13 [(size_t)2*HID_*DIM_];        // interleaved rows: 2j=w1[j], 2j+1=w3[j]
__device__ __half g_w2  [(size_t)DIM_*HID_];

// ---------------- helpers ----------------
__device__ __forceinline__ uint32_t smem_u32(const void* p){
    uint32_t a;
    asm("{ .reg .u64 t; cvta.to.shared.u64 t, %1; cvt.u32.u64 %0, t; }" : "=r"(a) : "l"(p));
    return a;
}
__device__ __forceinline__ uint32_t swz(uint32_t x){ return x ^ ((x >> 3) & 0x70); }
#define CP16(dst, src) asm volatile("cp.async.cg.shared.global [%0], [%1], 16;" :: "r"(dst), "l"(src))

__device__ __forceinline__ void ldsm4(uint32_t* r, uint32_t addr){
    asm volatile("ldmatrix.sync.aligned.m8n8.x4.shared.b16 {%0,%1,%2,%3}, [%4];"
        : "=r"(r[0]),"=r"(r[1]),"=r"(r[2]),"=r"(r[3]) : "r"(addr));
}
__device__ __forceinline__ void mma16816(float* c, const uint32_t* a, const uint32_t* b){
    asm volatile("mma.sync.aligned.m16n8k16.row.col.f32.f16.f16.f32 "
        "{%0,%1,%2,%3}, {%4,%5,%6,%7}, {%8,%9}, {%0,%1,%2,%3};"
        : "+f"(c[0]),"+f"(c[1]),"+f"(c[2]),"+f"(c[3])
        : "r"(a[0]),"r"(a[1]),"r"(a[2]),"r"(a[3]), "r"(b[0]),"r"(b[1]));
}
__device__ __forceinline__ uint32_t pack2h(float a, float b){
    __half2 h = __floats2half2_rn(a, b);
    return *reinterpret_cast<uint32_t*>(&h);
}

// =====================================================================
// fp16 mma.sync GEMM: C[m,n] (+epi) = sum_k A[m,k]*B[n,k]
// CTA 128 x 128, BK=64 (128B rows, SW128), 3-stage cp.async, 2 CTAs/SM.
// epi: 1 half-out, 4 swiglu-interleaved half-out (N/2 cols),
//      5 half-out with SCALE_ on cols < DIM_ (q part of qk GEMM),
//      6 half-out + fp32 residual Rv (wo), 7 fp32-out + half residual Rv (w2)
// =====================================================================
#define NSTAGE 3
#define BN_ 128

__global__ __launch_bounds__(256, 2) void mm_h(
    const __half* __restrict__ A, const __half* __restrict__ B, void* __restrict__ Cv,
    const void* __restrict__ Rv,
    int K, int lda, int ldb, int ldc, int epi)
{
    constexpr int WN = BN_ / 4;       // 32
    constexpr int NF = WN / 8;        // 4
    constexpr int STAGE = (128 + BN_) * 128;   // 32768 B
    constexpr int BI = BN_ / 32;      // 4

    extern __shared__ char smem[];
    const uint32_t sbase = (smem_u32(smem) + 127u) & ~127u;

    const int tid = threadIdx.x;
    const int wid = tid >> 5, lane = tid & 31;
    const int wm = (wid >> 2) * 64;
    const int wn = (wid & 3) * WN;
    const int bm = blockIdx.y * 128, bn = blockIdx.x * BN_;

    const int tA = lane >> 3;
    const int rA = (tA & 1) * 8 + (lane & 7);
    const int cA = tA >> 1;
    const int rB = (tA >> 1) * 8 + (lane & 7);
    const int cB = tA & 1;

    float acc[4][NF][4];
    #pragma unroll
    for (int i = 0; i < 4; i++)
        #pragma unroll
        for (int j = 0; j < NF; j++)
            { acc[i][j][0]=0.f; acc[i][j][1]=0.f; acc[i][j][2]=0.f; acc[i][j][3]=0.f; }

    const int nch = K >> 6;

    auto produce = [&](int c) {
        const uint32_t sA = sbase + (c % NSTAGE) * STAGE;
        const uint32_t sB = sA + 128 * 128;
        const int k0 = c << 6;
        #pragma unroll
        for (int i = 0; i < 4; i++) {
            int idx = tid + 256 * i; int row = idx >> 3, seg = idx & 7;
            CP16(sA + swz(row * 128 + seg * 16),
                 A + (size_t)(bm + row) * lda + k0 + seg * 8);
        }
        #pragma unroll
        for (int i = 0; i < BI; i++) {
            int idx = tid + 256 * i; int row = idx >> 3, seg = idx & 7;
            CP16(sB + swz(row * 128 + seg * 16),
                 B + (size_t)(bn + row) * ldb + k0 + seg * 8);
        }
        asm volatile("cp.async.commit_group;" ::: "memory");
    };

    produce(0);
    if (nch > 1) produce(1);

    for (int c = 0; c < nch; c++) {
        if (c < nch - 1) asm volatile("cp.async.wait_group 1;" ::: "memory");
        else             asm volatile("cp.async.wait_group 0;" ::: "memory");
        __syncthreads();
        if (c + 2 < nch) produce(c + 2);

        const uint32_t sA = sbase + (c % NSTAGE) * STAGE;
        const uint32_t sB = sA + 128 * 128;
        #pragma unroll
        for (int kk = 0; kk < 4; kk++) {
            uint32_t a[4][4];
            #pragma unroll
            for (int mf = 0; mf < 4; mf++) {
                const int row = wm + mf * 16 + rA;
                ldsm4(a[mf], sA + row * 128 + (((cA + 2*kk) ^ (rA & 7)) * 16));
            }
            uint32_t b[NF][2];
            #pragma unroll
            for (int nf2 = 0; nf2 < NF/2; nf2++) {
                uint32_t t[4];
                const int row = wn + nf2 * 16 + rB;
                ldsm4(t, sB + row * 128 + (((cB + 2*kk) ^ (rB & 7)) * 16));
                b[2*nf2][0]=t[0]; b[2*nf2][1]=t[1];
                b[2*nf2+1][0]=t[2]; b[2*nf2+1][1]=t[3];
            }
            #pragma unroll
            for (int mf = 0; mf < 4; mf++)
                #pragma unroll
                for (int nf = 0; nf < NF; nf++)
                    mma16816(acc[mf][nf], a[mf], b[nf]);
        }
    }
    __syncthreads();

    #pragma unroll
    for (int mf = 0; mf < 4; mf++) {
        const int r0 = bm + wm + mf * 16 + (lane >> 2);
        const int r1 = r0 + 8;
        #pragma unroll
        for (int nf = 0; nf < NF; nf++) {
            const int col = bn + wn + nf * 8 + (lane & 3) * 2;
            float2 v0 = make_float2(acc[mf][nf][0], acc[mf][nf][1]);
            float2 v1 = make_float2(acc[mf][nf][2], acc[mf][nf][3]);
            if (epi == 4) {
                __half* C = (__half*)Cv;
                float a0 = v0.x / (1.0f + __expf(-v0.x)) * v0.y;
                float a1 = v1.x / (1.0f + __expf(-v1.x)) * v1.y;
                C[(size_t)r0 * ldc + (col >> 1)] = __float2half_rn(a0);
                C[(size_t)r1 * ldc + (col >> 1)] = __float2half_rn(a1);
            } else if (epi == 1) {
                __half* C = (__half*)Cv;
                *(uint32_t*)(C + (size_t)r0 * ldc + col) = pack2h(v0.x, v0.y);
                *(uint32_t*)(C + (size_t)r1 * ldc + col) = pack2h(v1.x, v1.y);
            } else if (epi == 5) {
                __half* C = (__half*)Cv;
                const float sc = (col < DIM_) ? SCALE_ : 1.0f;
                *(uint32_t*)(C + (size_t)r0 * ldc + col) = pack2h(v0.x*sc, v0.y*sc);
                *(uint32_t*)(C + (size_t)r1 * ldc + col) = pack2h(v1.x*sc, v1.y*sc);
            } else if (epi == 6) {
                // half-out + fp32 residual (h1 = x + att@wo^T)
                __half* C = (__half*)Cv;
                const float* R = (const float*)Rv;
                float2 a0 = *(const float2*)(R + (size_t)r0 * ldc + col);
                float2 a1 = *(const float2*)(R + (size_t)r1 * ldc + col);
                *(uint32_t*)(C + (size_t)r0 * ldc + col) = pack2h(v0.x + a0.x, v0.y + a0.y);
                *(uint32_t*)(C + (size_t)r1 * ldc + col) = pack2h(v1.x + a1.x, v1.y + a1.y);
            } else {
                // epi 7: fp32-out + half residual (out = h1 + ff@w2^T)
                float* C = (float*)Cv;
                const __half* R = (const __half*)Rv;
                float2 a0 = __half22float2(*(const __half2*)(R + (size_t)r0 * ldc + col));
                float2 a1 = __half22float2(*(const __half2*)(R + (size_t)r1 * ldc + col));
                v0.x += a0.x; v0.y += a0.y;
                v1.x += a1.x; v1.y += a1.y;
                *(float2*)(C + (size_t)r0 * ldc + col) = v0;
                *(float2*)(C + (size_t)r1 * ldc + col) = v1;
            }
        }
    }
}

// =====================================================================
// Flash attention (fp16 in, fp32 softmax/accum). Q pre-scaled by 1/sqrt(d).
// R13 configuration (measured best): no online max, bm16 register prefetch,
// P staged through smem (pitch 144), double-buffered K/V.
// =====================================================================
#define FL_SMEM (106624)

__global__ __launch_bounds__(256, 2) void flash_k()
{
    extern __shared__ char smem[];
    const uint32_t sb = (smem_u32(smem) + 127u) & ~127u;

    const int tid = threadIdx.x;
    const int w = tid >> 5, lane = tid & 31;
    const int tA = lane >> 3;
    const int rA = (tA & 1) * 8 + (lane & 7);
    const int cA = tA >> 1;
    const int rB = (tA >> 1) * 8 + (lane & 7);
    const int cB = tA & 1;

    const int z = blockIdx.y, b = z >> 4, h = z & 15;
    const int bm = blockIdx.x * 128;

    const __half* qbase = g_qkv + (size_t)(b*S_ + bm) * (2*DIM_) + h*HD_;
    const __half* kbase = g_qkv + (size_t)(b*S_) * (2*DIM_) + DIM_ + h*HD_;
    const __half* vbase = g_vt + (size_t)h * HD_ * M_ + b*S_;   // row stride M_
    const __half* bmb   = g_bm16 + (size_t)h * S_ * S_;

    auto loadKV = [&](int kt, int buf) {
        const uint32_t ok = sb + 34816 + buf * 17408;
        const uint32_t ov = sb + 69632 + buf * 18432;
        #pragma unroll
        for (int i = 0; i < 4; i++) {       // K: 64 rows x 16 segs
            int idx = tid + 256*i; int r = idx >> 4, sg = idx & 15;
            CP16(ok + r*272 + sg*16, kbase + (size_t)(kt*64 + r) * (2*DIM_) + sg*8);
        }
        #pragma unroll
        for (int i = 0; i < 4; i++) {       // V: 128 d-rows x 8 segs
            int idx = tid + 256*i; int r = idx >> 3, sg = idx & 7;
            CP16(ov + r*144 + sg*16, vbase + (size_t)r * M_ + kt*64 + sg*8);
        }
        asm volatile("cp.async.commit_group;" ::: "memory");
    };

    // Q tile -> smem (128 rows x 16 segs, pitch 272)
    #pragma unroll
    for (int i = 0; i < 8; i++) {
        int idx = tid + 256*i; int r = idx >> 4, sg = idx & 15;
        CP16(sb + r*272 + sg*16, qbase + (size_t)r * (2*DIM_) + sg*8);
    }
    asm volatile("cp.async.commit_group;" ::: "memory");
    loadKV(0, 0);
    loadKV(1, 1);
    asm volatile("cp.async.wait_group 2;" ::: "memory");
    __syncthreads();

    uint32_t qf[8][4];
    #pragma unroll
    for (int kb = 0; kb < 8; kb++)
        ldsm4(qf[kb], sb + (w*16 + rA)*272 + (cA + 2*kb)*16);
    __syncthreads();

    const int gr0 = bm + w*16 + (lane >> 2);
    const int gr1 = gr0 + 8;
    const __half2* bm0 = (const __half2*)(bmb + (size_t)gr0*S_ + (lane & 3)*2);
    const __half2* bm1 = (const __half2*)(bmb + (size_t)gr1*S_ + (lane & 3)*2);

    float l0 = 0.f, l1 = 0.f;
    float oacc[16][4];
    #pragma unroll
    for (int i = 0; i < 16; i++)
        { oacc[i][0]=0.f; oacc[i][1]=0.f; oacc[i][2]=0.f; oacc[i][3]=0.f; }

    for (int kt = 0; kt < 32; kt++) {
        // ---- prefetch bm16 tile into registers (latency hidden by S-MMA) ----
        uint32_t bmv0[8], bmv1[8];
        #pragma unroll
        for (int nf = 0; nf < 8; nf++) {
            bmv0[nf] = *(const uint32_t*)(bm0 + (kt*32 + nf*4));
            bmv1[nf] = *(const uint32_t*)(bm1 + (kt*32 + nf*4));
        }

        if (kt < 31) asm volatile("cp.async.wait_group 1;" ::: "memory");
        else         asm volatile("cp.async.wait_group 0;" ::: "memory");
        __syncthreads();
        const int buf = kt & 1;
        const uint32_t ok = sb + 34816 + buf * 17408;
        const uint32_t ov = sb + 69632 + buf * 18432;

        // ---- S = Q @ K^T ----
        float sacc[8][4];
        #pragma unroll
        for (int i = 0; i < 8; i++)
            { sacc[i][0]=0.f; sacc[i][1]=0.f; sacc[i][2]=0.f; sacc[i][3]=0.f; }
        #pragma unroll
        for (int kb = 0; kb < 8; kb++) {
            #pragma unroll
            for (int nf2 = 0; nf2 < 4; nf2++) {
                uint32_t t[4];
                ldsm4(t, ok + (nf2*16 + rB)*272 + (cB + 2*kb)*16);
                uint32_t b0[2] = {t[0], t[1]}, b1[2] = {t[2], t[3]};
                mma16816(sacc[2*nf2],   qf[kb], b0);
                mma16816(sacc[2*nf2+1], qf[kb], b1);
            }
        }

        // ---- p = exp(s + bias+mask)  [no max subtraction needed] ----
        float rs0 = 0.f, rs1 = 0.f;
        float p[8][4];
        #pragma unroll
        for (int nf = 0; nf < 8; nf++) {
            float2 f0 = __half22float2(*(const __half2*)&bmv0[nf]);
            float2 f1 = __half22float2(*(const __half2*)&bmv1[nf]);
            p[nf][0] = __expf(sacc[nf][0] + f0.x);
            p[nf][1] = __expf(sacc[nf][1] + f0.y);
            p[nf][2] = __expf(sacc[nf][2] + f1.x);
            p[nf][3] = __expf(sacc[nf][3] + f1.y);
            rs0 += p[nf][0] + p[nf][1];
            rs1 += p[nf][2] + p[nf][3];
        }
        l0 += rs0;
        l1 += rs1;

        // ---- store P (fp16) to smem, pitch 144 ----
        {
            const uint32_t pr0 = sb + (w*16 + (lane>>2))*144 + (lane & 3)*4;
            #pragma unroll
            for (int nf = 0; nf < 8; nf++) {
                asm volatile("st.shared.u32 [%0], %1;" :: "r"(pr0 + nf*16), "r"(pack2h(p[nf][0], p[nf][1])) : "memory");
                asm volatile("st.shared.u32 [%0], %1;" :: "r"(pr0 + 8*144 + nf*16), "r"(pack2h(p[nf][2], p[nf][3])) : "memory");
            }
        }
        __syncwarp();

        // ---- O += P @ V ----
        #pragma unroll
        for (int kb = 0; kb < 4; kb++) {
            uint32_t pa[4];
            ldsm4(pa, sb + (w*16 + rA)*144 + (cA + 2*kb)*16);
            #pragma unroll
            for (int nf2 = 0; nf2 < 8; nf2++) {
                uint32_t t[4];
                ldsm4(t, ov + (nf2*16 + rB)*144 + (cB + 2*kb)*16);
                uint32_t b0[2] = {t[0], t[1]}, b1[2] = {t[2], t[3]};
                mma16816(oacc[2*nf2],   pa, b0);
                mma16816(oacc[2*nf2+1], pa, b1);
            }
        }
        __syncthreads();
        if (kt + 2 < 32) loadKV(kt + 2, buf);
    }

    // reduce l over the quad (lanes sharing a row)
    l0 += __shfl_xor_sync(0xffffffffu, l0, 1);
    l0 += __shfl_xor_sync(0xffffffffu, l0, 2);
    l1 += __shfl_xor_sync(0xffffffffu, l1, 1);
    l1 += __shfl_xor_sync(0xffffffffu, l1, 2);

    const float inv0 = 1.0f / l0, inv1 = 1.0f / l1;
    __half* o0 = g_att + (size_t)(b*S_ + gr0) * DIM_ + h*HD_;
    __half* o1 = g_att + (size_t)(b*S_ + gr1) * DIM_ + h*HD_;
    #pragma unroll
    for (int nfd = 0; nfd < 16; nfd++) {
        const int dc = nfd*8 + (lane & 3)*2;
        *(uint32_t*)(o0 + dc) = pack2h(oacc[nfd][0]*inv0, oacc[nfd][1]*inv0);
        *(uint32_t*)(o1 + dc) = pack2h(oacc[nfd][2]*inv1, oacc[nfd][3]*inv1);
    }
}

// ---------------- weight copy fp32 -> fp16 ----------------
__global__ __launch_bounds__(256) void cvt_h(const float* __restrict__ src,
                                             __half* __restrict__ dst, size_t n4)
{
    const size_t stride = (size_t)gridDim.x * 256;
    for (size_t i = (size_t)blockIdx.x * 256 + threadIdx.x; i < n4; i += stride) {
        float4 v = *(const float4*)(src + i * 4);
        __half2* d2 = (__half2*)(dst + i * 4);
        d2[0] = __floats2half2_rn(v.x, v.y);
        d2[1] = __floats2half2_rn(v.z, v.w);
    }
}

// ---------------- bm16 = half(bias + mask) ----------------
__global__ __launch_bounds__(256) void prep_bm(const float* __restrict__ bias,
                                               const float* __restrict__ mask,
                                               __half* __restrict__ dst)
{
    const size_t n4 = (size_t)NH_*S_*S_/4;
    const size_t stride = (size_t)gridDim.x * 256;
    for (size_t i = (size_t)blockIdx.x * 256 + threadIdx.x; i < n4; i += stride) {
        float4 bv = ((const float4*)bias)[i];
        float4 mv = ((const float4*)mask)[i & ((size_t)S_*S_/4 - 1)];
        __half2* d2 = (__half2*)(dst + i * 4);
        d2[0] = __floats2half2_rn(bv.x + mv.x, bv.y + mv.y);
        d2[1] = __floats2half2_rn(bv.z + mv.z, bv.w + mv.w);
    }
}

// ---------------- interleave w1/w3 rows -> fp16 ----------------
__global__ __launch_bounds__(256) void ilv_w13(const float* __restrict__ w1,
                                               const float* __restrict__ w3,
                                               __half* __restrict__ dst)
{
    const size_t idx = (size_t)blockIdx.x * 256 + threadIdx.x;   // 2*HID*512
    const size_t rr = idx >> 9, sg = idx & 511;
    const float* src = (rr & 1) ? w3 : w1;
    float4 v = *(const float4*)(src + (rr >> 1) * DIM_ + sg * 4);
    __half2* d2 = (__half2*)(dst + rr * DIM_ + sg * 4);
    d2[0] = __floats2half2_rn(v.x, v.y);
    d2[1] = __floats2half2_rn(v.z, v.w);
}

// ---------------- rmsnorm: fp32 in -> fp16 out ----------------
__global__ __launch_bounds__(256) void rmsnorm_k(const float* __restrict__ x,
                                                 const float* __restrict__ w,
                                                 __half* __restrict__ o)
{
    __shared__ float red[8];
    const size_t row = blockIdx.x;
    const float* xr = x + row * (size_t)DIM_;
    const int tid = threadIdx.x;
    float4 v0 = *(const float4*)(xr + tid*4);
    float4 v1 = *(const float4*)(xr + 1024 + tid*4);
    float s = v0.x*v0.x + v0.y*v0.y + v0.z*v0.z + v0.w*v0.w
            + v1.x*v1.x + v1.y*v1.y + v1.z*v1.z + v1.w*v1.w;
    #pragma unroll
    for (int off = 16; off > 0; off >>= 1) s += __shfl_xor_sync(0xffffffffu, s, off);
    if ((tid & 31) == 0) red[tid >> 5] = s;
    __syncthreads();
    s = red[0]+red[1]+red[2]+red[3]+red[4]+red[5]+red[6]+red[7];
    const float r = rsqrtf(s * (1.0f/DIM_) + EPS_);
    float4 w0 = *(const float4*)(w + tid*4);
    float4 w1 = *(const float4*)(w + 1024 + tid*4);
    __half2* orow = (__half2*)(o + row * (size_t)DIM_);
    orow[tid*2]          = __floats2half2_rn(v0.x*r*w0.x, v0.y*r*w0.y);
    orow[tid*2+1]        = __floats2half2_rn(v0.z*r*w0.z, v0.w*r*w0.w);
    orow[512 + tid*2]    = __floats2half2_rn(v1.x*r*w1.x, v1.y*r*w1.y);
    orow[512 + tid*2+1]  = __floats2half2_rn(v1.z*r*w1.z, v1.w*r*w1.w);
}

// ---------------- rmsnorm: fp16 in -> fp16 out ----------------
__global__ __launch_bounds__(256) void rmsnorm_h(const __half* __restrict__ x,
                                                 const float* __restrict__ w,
                                                 __half* __restrict__ o)
{
    __shared__ float red[8];
    const size_t row = blockIdx.x;
    const int tid = threadIdx.x;
    // 8 halves per thread (2048 / 256)
    const uint4 raw = *(const uint4*)(x + row * (size_t)DIM_ + tid * 8);
    float2 c0 = __half22float2(*(const __half2*)&raw.x);
    float2 c1 = __half22float2(*(const __half2*)&raw.y);
    float2 c2 = __half22float2(*(const __half2*)&raw.z);
    float2 c3 = __half22float2(*(const __half2*)&raw.w);
    float s = c0.x*c0.x + c0.y*c0.y + c1.x*c1.x + c1.y*c1.y
            + c2.x*c2.x + c2.y*c2.y + c3.x*c3.x + c3.y*c3.y;
    #pragma unroll
    for (int off = 16; off > 0; off >>= 1) s += __shfl_xor_sync(0xffffffffu, s, off);
    if ((tid & 31) == 0) red[tid >> 5] = s;
    __syncthreads();
    s = red[0]+red[1]+red[2]+red[3]+red[4]+red[5]+red[6]+red[7];
    const float r = rsqrtf(s * (1.0f/DIM_) + EPS_);
    float4 w0 = *(const float4*)(w + tid*8);
    float4 w1 = *(const float4*)(w + tid*8 + 4);
    __half2* orow = (__half2*)(o + row * (size_t)DIM_) + tid*4;
    orow[0] = __floats2half2_rn(c0.x*r*w0.x, c0.y*r*w0.y);
    orow[1] = __floats2half2_rn(c1.x*r*w0.z, c1.y*r*w0.w);
    orow[2] = __floats2half2_rn(c2.x*r*w1.x, c2.y*r*w1.y);
    orow[3] = __floats2half2_rn(c3.x*r*w1.z, c3.y*r*w1.w);
}

// ---------------- launch ----------------
extern "C" void kernel_launch(void* const* d_in, const int* in_sizes, int n_in,
                              void* d_out, int out_size)
{
    (void)in_sizes; (void)n_in; (void)out_size;
    const float* x    = (const float*)d_in[0];
    const float* mask = (const float*)d_in[1];
    const float* bias = (const float*)d_in[2];
    const float* wq   = (const float*)d_in[3];
    const float* wk   = (const float*)d_in[4];
    const float* wv   = (const float*)d_in[5];
    const float* wo   = (const float*)d_in[6];
    const float* w1   = (const float*)d_in[7];
    const float* w2   = (const float*)d_in[8];
    const float* w3   = (const float*)d_in[9];
    const float* anw  = (const float*)d_in[10];
    const float* fnw  = (const float*)d_in[11];
    float* out = (float*)d_out;

    __half *h, *qkv, *vt, *att, *h1, *f, *ff, *bm16, *cwqkv, *cwo, *cw13, *cw2;
    cudaGetSymbolAddress((void**)&h,    g_h);
    cudaGetSymbolAddress((void**)&qkv,  g_qkv);
    cudaGetSymbolAddress((void**)&vt,   g_vt);
    cudaGetSymbolAddress((void**)&att,  g_att);
    cudaGetSymbolAddress((void**)&h1,   g_h1);
    cudaGetSymbolAddress((void**)&f,    g_f);
    cudaGetSymbolAddress((void**)&ff,   g_ff);
    cudaGetSymbolAddress((void**)&bm16, g_bm16);
    cudaGetSymbolAddress((void**)&cwqkv,g_wqkv);
    cudaGetSymbolAddress((void**)&cwo,  g_wo);
    cudaGetSymbolAddress((void**)&cw13, g_w13);
    cudaGetSymbolAddress((void**)&cw2,  g_w2);

    const int SMH = NSTAGE * (128 + BN_) * 128 + 256;   // ~96.3 KB -> 2 CTAs/SM
    cudaFuncSetAttribute(mm_h, cudaFuncAttributeMaxDynamicSharedMemorySize, SMH);
    cudaFuncSetAttribute(flash_k, cudaFuncAttributeMaxDynamicSharedMemorySize, FL_SMEM);

    // ---- ONE side stream (R9-proven memory footprint; objects intentionally
    //      not destroyed: destroying mid-capture would invalidate the graph) ----
    cudaStream_t s1;
    cudaStreamCreate(&s1);
    cudaEvent_t eF, eQK, eV, eBM, eWo, eW13, eW2;
    cudaEventCreateWithFlags(&eF,   cudaEventDisableTiming);
    cudaEventCreateWithFlags(&eQK,  cudaEventDisableTiming);
    cudaEventCreateWithFlags(&eV,   cudaEventDisableTiming);
    cudaEventCreateWithFlags(&eBM,  cudaEventDisableTiming);
    cudaEventCreateWithFlags(&eWo,  cudaEventDisableTiming);
    cudaEventCreateWithFlags(&eW13, cudaEventDisableTiming);
    cudaEventCreateWithFlags(&eW2,  cudaEventDisableTiming);

    cudaEventRecord(eF, 0);
    cudaStreamWaitEvent(s1, eF, 0);

    cvt_h<<<1024, 256, 0, s1>>>(wq, cwqkv,                       (size_t)DIM_*DIM_/4);
    cvt_h<<<1024, 256, 0, s1>>>(wk, cwqkv + (size_t)DIM_*DIM_,   (size_t)DIM_*DIM_/4);
    cudaEventRecord(eQK, s1);
    cvt_h<<<1024, 256, 0, s1>>>(wv, cwqkv + (size_t)2*DIM_*DIM_, (size_t)DIM_*DIM_/4);
    cudaEventRecord(eV, s1);
    prep_bm<<<2048, 256, 0, s1>>>(bias, mask, bm16);
    cudaEventRecord(eBM, s1);
    cvt_h<<<1024, 256, 0, s1>>>(wo, cwo,                         (size_t)DIM_*DIM_/4);
    cudaEventRecord(eWo, s1);
    ilv_w13<<<(unsigned)((size_t)2*HID_*512/256), 256, 0, s1>>>(w1, w3, cw13);
    cudaEventRecord(eW13, s1);
    cvt_h<<<1024, 256, 0, s1>>>(w2, cw2,                         (size_t)DIM_*HID_/4);
    cudaEventRecord(eW2, s1);

    // ---- mainline (default stream) — R9/R13 ordering ----
    rmsnorm_k<<<M_, 256>>>(x, anw, h);
    // qk: [M, 4096] = h @ [wq;wk]^T, q cols pre-scaled
    cudaStreamWaitEvent(0, eQK, 0);
    mm_h<<<dim3(2*DIM_/BN_, M_/128), 256, SMH>>>(
        h, cwqkv, qkv, nullptr, DIM_, DIM_, DIM_, 2*DIM_, 5);
    // vt: [2048 d, 4096 tokens] = wv @ h^T (transposed-V GEMM)
    cudaStreamWaitEvent(0, eV, 0);
    mm_h<<<dim3(M_/BN_, DIM_/128), 256, SMH>>>(
        cwqkv + (size_t)2*DIM_*DIM_, h, vt, nullptr, DIM_, DIM_, DIM_, M_, 1);
    cudaStreamWaitEvent(0, eBM, 0);
    flash_k<<<dim3(S_/128, B_*NH_), 256, FL_SMEM>>>();
    cudaStreamWaitEvent(0, eWo, 0);
    // h1 (fp16) = x (fp32) + att @ wo^T
    mm_h<<<dim3(DIM_/BN_, M_/128), 256, SMH>>>(
        att, cwo, h1, x, DIM_, DIM_, DIM_, DIM_, 6);

    // --- FFN ---
    rmsnorm_h<<<M_, 256>>>(h1, fnw, f);
    cudaStreamWaitEvent(0, eW13, 0);
    mm_h<<<dim3(2*HID_/BN_, M_/128), 256, SMH>>>(
        f, cw13, ff, nullptr, DIM_, DIM_, DIM_, HID_, 4);
    cudaStreamWaitEvent(0, eW2, 0);
    // out (fp32) = h1 (fp16) + ff @ w2^T
    mm_h<<<dim3(DIM_/BN_, M_/128), 256, SMH>>>(
        ff, cw2, out, h1, HID_, HID_, HID_, DIM_, 7);
}

// round 17
// speedup vs baseline: 1.0108x; 1.0060x over previous
#include <cuda_runtime.h>
#include <cuda_fp16.h>
#include <math.h>
#include <stdint.h>

// ---------------- problem constants ----------------
#define B_    2
#define S_    2048
#define DIM_  2048
#define NH_   16
#define HD_   128
#define HID_  5632
#define M_    (B_*S_)
#define EPS_  1e-5f
#define SCALE_ 0.08838834764831845f   // 1/sqrt(128)

// ---------------- scratch (device globals; no allocation) ----------------
__device__ __half g_h   [(size_t)M_*DIM_];
__device__ __half g_qkv [(size_t)M_*2*DIM_];          // [m][q|k]  (row stride 2*DIM)
__device__ __half g_vt  [(size_t)NH_*HD_*M_];         // [h*128+d][b*S+s]
__device__ __half g_att [(size_t)M_*DIM_];
__device__ float  g_h1  [(size_t)M_*DIM_];
__device__ __half g_f   [(size_t)M_*DIM_];
__device__ __half g_ff  [(size_t)M_*HID_];
__device__ __half g_bm16[(size_t)NH_*S_*S_];          // half(bias + mask)
// fp16 weight copies
__device__ __half g_wqkv[(size_t)3*DIM_*DIM_];        // wq | wk | wv
__device__ __half g_wo  [(size_t)DIM_*DIM_];
__device__ __half g_w13 [(size_t)2*HID_*DIM_];        // interleaved rows: 2j=w1[j], 2j+1=w3[j]
__device__ __half g_w2  [(size_t)DIM_*HID_];

// ---------------- helpers ----------------
__device__ __forceinline__ uint32_t smem_u32(const void* p){
    uint32_t a;
    asm("{ .reg .u64 t; cvta.to.shared.u64 t, %1; cvt.u32.u64 %0, t; }" : "=r"(a) : "l"(p));
    return a;
}
__device__ __forceinline__ uint32_t swz(uint32_t x){ return x ^ ((x >> 3) & 0x70); }
#define CP16(dst, src) asm volatile("cp.async.cg.shared.global [%0], [%1], 16;" :: "r"(dst), "l"(src))

__device__ __forceinline__ void ldsm4(uint32_t* r, uint32_t addr){
    asm volatile("ldmatrix.sync.aligned.m8n8.x4.shared.b16 {%0,%1,%2,%3}, [%4];"
        : "=r"(r[0]),"=r"(r[1]),"=r"(r[2]),"=r"(r[3]) : "r"(addr));
}
__device__ __forceinline__ void mma16816(float* c, const uint32_t* a, const uint32_t* b){
    asm volatile("mma.sync.aligned.m16n8k16.row.col.f32.f16.f16.f32 "
        "{%0,%1,%2,%3}, {%4,%5,%6,%7}, {%8,%9}, {%0,%1,%2,%3};"
        : "+f"(c[0]),"+f"(c[1]),"+f"(c[2]),"+f"(c[3])
        : "r"(a[0]),"r"(a[1]),"r"(a[2]),"r"(a[3]), "r"(b[0]),"r"(b[1]));
}
__device__ __forceinline__ uint32_t pack2h(float a, float b){
    __half2 h = __floats2half2_rn(a, b);
    return *reinterpret_cast<uint32_t*>(&h);
}

// =====================================================================
// fp16 mma.sync GEMM: C[m,n] (+epi) = sum_k A[m,k]*B[n,k]
// CTA 128 x 128, BK=64 (128B rows, SW128), 3-stage cp.async, 2 CTAs/SM.
// epi: 1 half-out, 2 fp32-out + residual Rb, 4 swiglu-interleaved (N/2 cols),
//      5 half-out with SCALE_ on cols < DIM_ (q part of qk GEMM)
// =====================================================================
#define NSTAGE 3
#define BN_ 128

__global__ __launch_bounds__(256, 2) void mm_h(
    const __half* __restrict__ A, const __half* __restrict__ B, void* __restrict__ Cv,
    const float* __restrict__ Rb,
    int K, int lda, int ldb, int ldc, int epi)
{
    constexpr int WN = BN_ / 4;       // 32
    constexpr int NF = WN / 8;        // 4
    constexpr int STAGE = (128 + BN_) * 128;   // 32768 B
    constexpr int BI = BN_ / 32;      // 4

    extern __shared__ char smem[];
    const uint32_t sbase = (smem_u32(smem) + 127u) & ~127u;

    const int tid = threadIdx.x;
    const int wid = tid >> 5, lane = tid & 31;
    const int wm = (wid >> 2) * 64;
    const int wn = (wid & 3) * WN;
    const int bm = blockIdx.y * 128, bn = blockIdx.x * BN_;

    const int tA = lane >> 3;
    const int rA = (tA & 1) * 8 + (lane & 7);
    const int cA = tA >> 1;
    const int rB = (tA >> 1) * 8 + (lane & 7);
    const int cB = tA & 1;

    float acc[4][NF][4];
    #pragma unroll
    for (int i = 0; i < 4; i++)
        #pragma unroll
        for (int j = 0; j < NF; j++)
            { acc[i][j][0]=0.f; acc[i][j][1]=0.f; acc[i][j][2]=0.f; acc[i][j][3]=0.f; }

    const int nch = K >> 6;

    auto produce = [&](int c) {
        const uint32_t sA = sbase + (c % NSTAGE) * STAGE;
        const uint32_t sB = sA + 128 * 128;
        const int k0 = c << 6;
        #pragma unroll
        for (int i = 0; i < 4; i++) {
            int idx = tid + 256 * i; int row = idx >> 3, seg = idx & 7;
            CP16(sA + swz(row * 128 + seg * 16),
                 A + (size_t)(bm + row) * lda + k0 + seg * 8);
        }
        #pragma unroll
        for (int i = 0; i < BI; i++) {
            int idx = tid + 256 * i; int row = idx >> 3, seg = idx & 7;
            CP16(sB + swz(row * 128 + seg * 16),
                 B + (size_t)(bn + row) * ldb + k0 + seg * 8);
        }
        asm volatile("cp.async.commit_group;" ::: "memory");
    };

    produce(0);
    if (nch > 1) produce(1);

    for (int c = 0; c < nch; c++) {
        if (c < nch - 1) asm volatile("cp.async.wait_group 1;" ::: "memory");
        else             asm volatile("cp.async.wait_group 0;" ::: "memory");
        __syncthreads();
        if (c + 2 < nch) produce(c + 2);

        const uint32_t sA = sbase + (c % NSTAGE) * STAGE;
        const uint32_t sB = sA + 128 * 128;
        #pragma unroll
        for (int kk = 0; kk < 4; kk++) {
            uint32_t a[4][4];
            #pragma unroll
            for (int mf = 0; mf < 4; mf++) {
                const int row = wm + mf * 16 + rA;
                ldsm4(a[mf], sA + row * 128 + (((cA + 2*kk) ^ (rA & 7)) * 16));
            }
            uint32_t b[NF][2];
            #pragma unroll
            for (int nf2 = 0; nf2 < NF/2; nf2++) {
                uint32_t t[4];
                const int row = wn + nf2 * 16 + rB;
                ldsm4(t, sB + row * 128 + (((cB + 2*kk) ^ (rB & 7)) * 16));
                b[2*nf2][0]=t[0]; b[2*nf2][1]=t[1];
                b[2*nf2+1][0]=t[2]; b[2*nf2+1][1]=t[3];
            }
            #pragma unroll
            for (int mf = 0; mf < 4; mf++)
                #pragma unroll
                for (int nf = 0; nf < NF; nf++)
                    mma16816(acc[mf][nf], a[mf], b[nf]);
        }
    }
    __syncthreads();

    #pragma unroll
    for (int mf = 0; mf < 4; mf++) {
        const int r0 = bm + wm + mf * 16 + (lane >> 2);
        const int r1 = r0 + 8;
        #pragma unroll
        for (int nf = 0; nf < NF; nf++) {
            const int col = bn + wn + nf * 8 + (lane & 3) * 2;
            float2 v0 = make_float2(acc[mf][nf][0], acc[mf][nf][1]);
            float2 v1 = make_float2(acc[mf][nf][2], acc[mf][nf][3]);
            if (epi == 4) {
                __half* C = (__half*)Cv;
                float a0 = v0.x / (1.0f + __expf(-v0.x)) * v0.y;
                float a1 = v1.x / (1.0f + __expf(-v1.x)) * v1.y;
                C[(size_t)r0 * ldc + (col >> 1)] = __float2half_rn(a0);
                C[(size_t)r1 * ldc + (col >> 1)] = __float2half_rn(a1);
            } else if (epi == 1) {
                __half* C = (__half*)Cv;
                *(uint32_t*)(C + (size_t)r0 * ldc + col) = pack2h(v0.x, v0.y);
                *(uint32_t*)(C + (size_t)r1 * ldc + col) = pack2h(v1.x, v1.y);
            } else if (epi == 5) {
                __half* C = (__half*)Cv;
                const float sc = (col < DIM_) ? SCALE_ : 1.0f;
                *(uint32_t*)(C + (size_t)r0 * ldc + col) = pack2h(v0.x*sc, v0.y*sc);
                *(uint32_t*)(C + (size_t)r1 * ldc + col) = pack2h(v1.x*sc, v1.y*sc);
            } else {
                float* C = (float*)Cv;
                float2 a0 = *(const float2*)(Rb + (size_t)r0 * ldc + col);
                float2 a1 = *(const float2*)(Rb + (size_t)r1 * ldc + col);
                v0.x += a0.x; v0.y += a0.y;
                v1.x += a1.x; v1.y += a1.y;
                *(float2*)(C + (size_t)r0 * ldc + col) = v0;
                *(float2*)(C + (size_t)r1 * ldc + col) = v1;
            }
        }
    }
}

// =====================================================================
// Flash attention (fp16 in, fp32 softmax/accum). Q pre-scaled by 1/sqrt(d).
// R13 configuration (measured best): no online max, bm16 register prefetch,
// P staged through smem (pitch 144), double-buffered K/V.
// =====================================================================
#define FL_SMEM (106624)

__global__ __launch_bounds__(256, 2) void flash_k()
{
    extern __shared__ char smem[];
    const uint32_t sb = (smem_u32(smem) + 127u) & ~127u;

    const int tid = threadIdx.x;
    const int w = tid >> 5, lane = tid & 31;
    const int tA = lane >> 3;
    const int rA = (tA & 1) * 8 + (lane & 7);
    const int cA = tA >> 1;
    const int rB = (tA >> 1) * 8 + (lane & 7);
    const int cB = tA & 1;

    const int z = blockIdx.y, b = z >> 4, h = z & 15;
    const int bm = blockIdx.x * 128;

    const __half* qbase = g_qkv + (size_t)(b*S_ + bm) * (2*DIM_) + h*HD_;
    const __half* kbase = g_qkv + (size_t)(b*S_) * (2*DIM_) + DIM_ + h*HD_;
    const __half* vbase = g_vt + (size_t)h * HD_ * M_ + b*S_;   // row stride M_
    const __half* bmb   = g_bm16 + (size_t)h * S_ * S_;

    auto loadKV = [&](int kt, int buf) {
        const uint32_t ok = sb + 34816 + buf * 17408;
        const uint32_t ov = sb + 69632 + buf * 18432;
        #pragma unroll
        for (int i = 0; i < 4; i++) {       // K: 64 rows x 16 segs
            int idx = tid + 256*i; int r = idx >> 4, sg = idx & 15;
            CP16(ok + r*272 + sg*16, kbase + (size_t)(kt*64 + r) * (2*DIM_) + sg*8);
        }
        #pragma unroll
        for (int i = 0; i < 4; i++) {       // V: 128 d-rows x 8 segs
            int idx = tid + 256*i; int r = idx >> 3, sg = idx & 7;
            CP16(ov + r*144 + sg*16, vbase + (size_t)r * M_ + kt*64 + sg*8);
        }
        asm volatile("cp.async.commit_group;" ::: "memory");
    };

    // Q tile -> smem (128 rows x 16 segs, pitch 272)
    #pragma unroll
    for (int i = 0; i < 8; i++) {
        int idx = tid + 256*i; int r = idx >> 4, sg = idx & 15;
        CP16(sb + r*272 + sg*16, qbase + (size_t)r * (2*DIM_) + sg*8);
    }
    asm volatile("cp.async.commit_group;" ::: "memory");
    loadKV(0, 0);
    loadKV(1, 1);
    asm volatile("cp.async.wait_group 2;" ::: "memory");
    __syncthreads();

    uint32_t qf[8][4];
    #pragma unroll
    for (int kb = 0; kb < 8; kb++)
        ldsm4(qf[kb], sb + (w*16 + rA)*272 + (cA + 2*kb)*16);
    __syncthreads();

    const int gr0 = bm + w*16 + (lane >> 2);
    const int gr1 = gr0 + 8;
    const __half2* bm0 = (const __half2*)(bmb + (size_t)gr0*S_ + (lane & 3)*2);
    const __half2* bm1 = (const __half2*)(bmb + (size_t)gr1*S_ + (lane & 3)*2);

    float l0 = 0.f, l1 = 0.f;
    float oacc[16][4];
    #pragma unroll
    for (int i = 0; i < 16; i++)
        { oacc[i][0]=0.f; oacc[i][1]=0.f; oacc[i][2]=0.f; oacc[i][3]=0.f; }

    for (int kt = 0; kt < 32; kt++) {
        // ---- prefetch bm16 tile into registers (latency hidden by S-MMA) ----
        uint32_t bmv0[8], bmv1[8];
        #pragma unroll
        for (int nf = 0; nf < 8; nf++) {
            bmv0[nf] = *(const uint32_t*)(bm0 + (kt*32 + nf*4));
            bmv1[nf] = *(const uint32_t*)(bm1 + (kt*32 + nf*4));
        }

        if (kt < 31) asm volatile("cp.async.wait_group 1;" ::: "memory");
        else         asm volatile("cp.async.wait_group 0;" ::: "memory");
        __syncthreads();
        const int buf = kt & 1;
        const uint32_t ok = sb + 34816 + buf * 17408;
        const uint32_t ov = sb + 69632 + buf * 18432;

        // ---- S = Q @ K^T ----
        float sacc[8][4];
        #pragma unroll
        for (int i = 0; i < 8; i++)
            { sacc[i][0]=0.f; sacc[i][1]=0.f; sacc[i][2]=0.f; sacc[i][3]=0.f; }
        #pragma unroll
        for (int kb = 0; kb < 8; kb++) {
            #pragma unroll
            for (int nf2 = 0; nf2 < 4; nf2++) {
                uint32_t t[4];
                ldsm4(t, ok + (nf2*16 + rB)*272 + (cB + 2*kb)*16);
                uint32_t b0[2] = {t[0], t[1]}, b1[2] = {t[2], t[3]};
                mma16816(sacc[2*nf2],   qf[kb], b0);
                mma16816(sacc[2*nf2+1], qf[kb], b1);
            }
        }

        // ---- p = exp(s + bias+mask)  [no max subtraction needed] ----
        float rs0 = 0.f, rs1 = 0.f;
        float p[8][4];
        #pragma unroll
        for (int nf = 0; nf < 8; nf++) {
            float2 f0 = __half22float2(*(const __half2*)&bmv0[nf]);
            float2 f1 = __half22float2(*(const __half2*)&bmv1[nf]);
            p[nf][0] = __expf(sacc[nf][0] + f0.x);
            p[nf][1] = __expf(sacc[nf][1] + f0.y);
            p[nf][2] = __expf(sacc[nf][2] + f1.x);
            p[nf][3] = __expf(sacc[nf][3] + f1.y);
            rs0 += p[nf][0] + p[nf][1];
            rs1 += p[nf][2] + p[nf][3];
        }
        l0 += rs0;
        l1 += rs1;

        // ---- store P (fp16) to smem, pitch 144 ----
        {
            const uint32_t pr0 = sb + (w*16 + (lane>>2))*144 + (lane & 3)*4;
            #pragma unroll
            for (int nf = 0; nf < 8; nf++) {
                asm volatile("st.shared.u32 [%0], %1;" :: "r"(pr0 + nf*16), "r"(pack2h(p[nf][0], p[nf][1])) : "memory");
                asm volatile("st.shared.u32 [%0], %1;" :: "r"(pr0 + 8*144 + nf*16), "r"(pack2h(p[nf][2], p[nf][3])) : "memory");
            }
        }
        __syncwarp();

        // ---- O += P @ V ----
        #pragma unroll
        for (int kb = 0; kb < 4; kb++) {
            uint32_t pa[4];
            ldsm4(pa, sb + (w*16 + rA)*144 + (cA + 2*kb)*16);
            #pragma unroll
            for (int nf2 = 0; nf2 < 8; nf2++) {
                uint32_t t[4];
                ldsm4(t, ov + (nf2*16 + rB)*144 + (cB + 2*kb)*16);
                uint32_t b0[2] = {t[0], t[1]}, b1[2] = {t[2], t[3]};
                mma16816(oacc[2*nf2],   pa, b0);
                mma16816(oacc[2*nf2+1], pa, b1);
            }
        }
        __syncthreads();
        if (kt + 2 < 32) loadKV(kt + 2, buf);
    }

    // reduce l over the quad (lanes sharing a row)
    l0 += __shfl_xor_sync(0xffffffffu, l0, 1);
    l0 += __shfl_xor_sync(0xffffffffu, l0, 2);
    l1 += __shfl_xor_sync(0xffffffffu, l1, 1);
    l1 += __shfl_xor_sync(0xffffffffu, l1, 2);

    const float inv0 = 1.0f / l0, inv1 = 1.0f / l1;
    __half* o0 = g_att + (size_t)(b*S_ + gr0) * DIM_ + h*HD_;
    __half* o1 = g_att + (size_t)(b*S_ + gr1) * DIM_ + h*HD_;
    #pragma unroll
    for (int nfd = 0; nfd < 16; nfd++) {
        const int dc = nfd*8 + (lane & 3)*2;
        *(uint32_t*)(o0 + dc) = pack2h(oacc[nfd][0]*inv0, oacc[nfd][1]*inv0);
        *(uint32_t*)(o1 + dc) = pack2h(oacc[nfd][2]*inv1, oacc[nfd][3]*inv1);
    }
}

// ---------------- weight copy fp32 -> fp16 ----------------
__global__ __launch_bounds__(256) void cvt_h(const float* __restrict__ src,
                                             __half* __restrict__ dst, size_t n4)
{
    const size_t stride = (size_t)gridDim.x * 256;
    for (size_t i = (size_t)blockIdx.x * 256 + threadIdx.x; i < n4; i += stride) {
        float4 v = *(const float4*)(src + i * 4);
        __half2* d2 = (__half2*)(dst + i * 4);
        d2[0] = __floats2half2_rn(v.x, v.y);
        d2[1] = __floats2half2_rn(v.z, v.w);
    }
}

// ---------------- bm16 = half(bias + mask) ----------------
__global__ __launch_bounds__(256) void prep_bm(const float* __restrict__ bias,
                                               const float* __restrict__ mask,
                                               __half* __restrict__ dst)
{
    const size_t n4 = (size_t)NH_*S_*S_/4;
    const size_t stride = (size_t)gridDim.x * 256;
    for (size_t i = (size_t)blockIdx.x * 256 + threadIdx.x; i < n4; i += stride) {
        float4 bv = ((const float4*)bias)[i];
        float4 mv = ((const float4*)mask)[i & ((size_t)S_*S_/4 - 1)];
        __half2* d2 = (__half2*)(dst + i * 4);
        d2[0] = __floats2half2_rn(bv.x + mv.x, bv.y + mv.y);
        d2[1] = __floats2half2_rn(bv.z + mv.z, bv.w + mv.w);
    }
}

// ---------------- interleave w1/w3 rows -> fp16 ----------------
__global__ __launch_bounds__(256) void ilv_w13(const float* __restrict__ w1,
                                               const float* __restrict__ w3,
                                               __half* __restrict__ dst)
{
    const size_t idx = (size_t)blockIdx.x * 256 + threadIdx.x;   // 2*HID*512
    const size_t rr = idx >> 9, sg = idx & 511;
    const float* src = (rr & 1) ? w3 : w1;
    float4 v = *(const float4*)(src + (rr >> 1) * DIM_ + sg * 4);
    __half2* d2 = (__half2*)(dst + rr * DIM_ + sg * 4);
    d2[0] = __floats2half2_rn(v.x, v.y);
    d2[1] = __floats2half2_rn(v.z, v.w);
}

// ---------------- rmsnorm: fp32 in -> fp16 out ----------------
__global__ __launch_bounds__(256) void rmsnorm_k(const float* __restrict__ x,
                                                 const float* __restrict__ w,
                                                 __half* __restrict__ o)
{
    __shared__ float red[8];
    const size_t row = blockIdx.x;
    const float* xr = x + row * (size_t)DIM_;
    const int tid = threadIdx.x;
    float4 v0 = *(const float4*)(xr + tid*4);
    float4 v1 = *(const float4*)(xr + 1024 + tid*4);
    float s = v0.x*v0.x + v0.y*v0.y + v0.z*v0.z + v0.w*v0.w
            + v1.x*v1.x + v1.y*v1.y + v1.z*v1.z + v1.w*v1.w;
    #pragma unroll
    for (int off = 16; off > 0; off >>= 1) s += __shfl_xor_sync(0xffffffffu, s, off);
    if ((tid & 31) == 0) red[tid >> 5] = s;
    __syncthreads();
    s = red[0]+red[1]+red[2]+red[3]+red[4]+red[5]+red[6]+red[7];
    const float r = rsqrtf(s * (1.0f/DIM_) + EPS_);
    float4 w0 = *(const float4*)(w + tid*4);
    float4 w1 = *(const float4*)(w + 1024 + tid*4);
    __half2* orow = (__half2*)(o + row * (size_t)DIM_);
    orow[tid*2]          = __floats2half2_rn(v0.x*r*w0.x, v0.y*r*w0.y);
    orow[tid*2+1]        = __floats2half2_rn(v0.z*r*w0.z, v0.w*r*w0.w);
    orow[512 + tid*2]    = __floats2half2_rn(v1.x*r*w1.x, v1.y*r*w1.y);
    orow[512 + tid*2+1]  = __floats2half2_rn(v1.z*r*w1.z, v1.w*r*w1.w);
}

// ---------------- launch ----------------
extern "C" void kernel_launch(void* const* d_in, const int* in_sizes, int n_in,
                              void* d_out, int out_size)
{
    (void)in_sizes; (void)n_in; (void)out_size;
    const float* x    = (const float*)d_in[0];
    const float* mask = (const float*)d_in[1];
    const float* bias = (const float*)d_in[2];
    const float* wq   = (const float*)d_in[3];
    const float* wk   = (const float*)d_in[4];
    const float* wv   = (const float*)d_in[5];
    const float* wo   = (const float*)d_in[6];
    const float* w1   = (const float*)d_in[7];
    const float* w2   = (const float*)d_in[8];
    const float* w3   = (const float*)d_in[9];
    const float* anw  = (const float*)d_in[10];
    const float* fnw  = (const float*)d_in[11];
    float* out = (float*)d_out;

    __half *h, *qkv, *vt, *att, *f, *ff, *bm16, *cwqkv, *cwo, *cw13, *cw2;
    float *h1;
    cudaGetSymbolAddress((void**)&h,    g_h);
    cudaGetSymbolAddress((void**)&qkv,  g_qkv);
    cudaGetSymbolAddress((void**)&vt,   g_vt);
    cudaGetSymbolAddress((void**)&att,  g_att);
    cudaGetSymbolAddress((void**)&h1,   g_h1);
    cudaGetSymbolAddress((void**)&f,    g_f);
    cudaGetSymbolAddress((void**)&ff,   g_ff);
    cudaGetSymbolAddress((void**)&bm16, g_bm16);
    cudaGetSymbolAddress((void**)&cwqkv,g_wqkv);
    cudaGetSymbolAddress((void**)&cwo,  g_wo);
    cudaGetSymbolAddress((void**)&cw13, g_w13);
    cudaGetSymbolAddress((void**)&cw2,  g_w2);

    const int SMH = NSTAGE * (128 + BN_) * 128 + 256;   // ~96.3 KB -> 2 CTAs/SM
    cudaFuncSetAttribute(mm_h, cudaFuncAttributeMaxDynamicSharedMemorySize, SMH);
    cudaFuncSetAttribute(flash_k, cudaFuncAttributeMaxDynamicSharedMemorySize, FL_SMEM);

    // ---- ONE side stream (R9-proven memory footprint; objects intentionally
    //      not destroyed: destroying mid-capture would invalidate the graph) ----
    cudaStream_t s1;
    cudaStreamCreate(&s1);
    cudaEvent_t eF, eQK, eV, eBM, eWo, eW13, eW2, eFA, eOut;
    cudaEventCreateWithFlags(&eF,   cudaEventDisableTiming);
    cudaEventCreateWithFlags(&eQK,  cudaEventDisableTiming);
    cudaEventCreateWithFlags(&eV,   cudaEventDisableTiming);
    cudaEventCreateWithFlags(&eBM,  cudaEventDisableTiming);
    cudaEventCreateWithFlags(&eWo,  cudaEventDisableTiming);
    cudaEventCreateWithFlags(&eW13, cudaEventDisableTiming);
    cudaEventCreateWithFlags(&eW2,  cudaEventDisableTiming);
    cudaEventCreateWithFlags(&eFA,  cudaEventDisableTiming);
    cudaEventCreateWithFlags(&eOut, cudaEventDisableTiming);

    cudaEventRecord(eF, 0);
    cudaStreamWaitEvent(s1, eF, 0);

    cvt_h<<<1024, 256, 0, s1>>>(wq, cwqkv,                       (size_t)DIM_*DIM_/4);
    cvt_h<<<1024, 256, 0, s1>>>(wk, cwqkv + (size_t)DIM_*DIM_,   (size_t)DIM_*DIM_/4);
    cudaEventRecord(eQK, s1);
    cvt_h<<<1024, 256, 0, s1>>>(wv, cwqkv + (size_t)2*DIM_*DIM_, (size_t)DIM_*DIM_/4);
    cudaEventRecord(eV, s1);
    prep_bm<<<2048, 256, 0, s1>>>(bias, mask, bm16);
    cudaEventRecord(eBM, s1);
    cvt_h<<<1024, 256, 0, s1>>>(wo, cwo,                         (size_t)DIM_*DIM_/4);
    cudaEventRecord(eWo, s1);
    ilv_w13<<<(unsigned)((size_t)2*HID_*512/256), 256, 0, s1>>>(w1, w3, cw13);
    cudaEventRecord(eW13, s1);
    cvt_h<<<1024, 256, 0, s1>>>(w2, cw2,                         (size_t)DIM_*HID_/4);
    cudaEventRecord(eW2, s1);

    // ---- mainline (default stream) — R9/R13 ordering ----
    rmsnorm_k<<<M_, 256>>>(x, anw, h);
    // qk: [M, 4096] = h @ [wq;wk]^T, q cols pre-scaled
    cudaStreamWaitEvent(0, eQK, 0);
    mm_h<<<dim3(2*DIM_/BN_, M_/128), 256, SMH>>>(
        h, cwqkv, qkv, nullptr, DIM_, DIM_, DIM_, 2*DIM_, 5);
    // vt: [2048 d, 4096 tokens] = wv @ h^T (transposed-V GEMM)
    cudaStreamWaitEvent(0, eV, 0);
    mm_h<<<dim3(M_/BN_, DIM_/128), 256, SMH>>>(
        cwqkv + (size_t)2*DIM_*DIM_, h, vt, nullptr, DIM_, DIM_, DIM_, M_, 1);
    cudaStreamWaitEvent(0, eBM, 0);
    flash_k<<<dim3(S_/128, B_*NH_), 256, FL_SMEM>>>();
    cudaStreamWaitEvent(0, eWo, 0);
    mm_h<<<dim3(DIM_/BN_, M_/128), 256, SMH>>>(
        att, cwo, h1, x, DIM_, DIM_, DIM_, DIM_, 2);

    // --- FFN (M-split pipelined: w13_lo -> [w13_hi || w2_lo(s1)] -> w2_hi) ---
    rmsnorm_k<<<M_, 256>>>(h1, fnw, f);
    cudaStreamWaitEvent(0, eW13, 0);
    const int MH = M_ / 2;   // 2048 rows per half
    // w13_lo: rows [0, 2048)
    mm_h<<<dim3(2*HID_/BN_, MH/128), 256, SMH>>>(
        f, cw13, ff, nullptr, DIM_, DIM_, DIM_, HID_, 4);
    cudaEventRecord(eFA, 0);
    // w13_hi: rows [2048, 4096)
    mm_h<<<dim3(2*HID_/BN_, MH/128), 256, SMH>>>(
        f + (size_t)MH*DIM_, cw13, ff + (size_t)MH*HID_, nullptr,
        DIM_, DIM_, DIM_, HID_, 4);
    // w2_lo on s1, concurrent with w13_hi (s1 idle since prep; cw2 ready by
    // s1 stream order). out rows [0, 2048) = h1 + ff_lo @ w2^T
    cudaStreamWaitEvent(s1, eFA, 0);
    mm_h<<<dim3(DIM_/BN_, MH/128), 256, SMH, s1>>>(
        ff, cw2, out, h1, HID_, HID_, HID_, DIM_, 2);
    cudaEventRecord(eOut, s1);
    // w2_hi on mainline: out rows [2048, 4096)
    cudaStreamWaitEvent(0, eW2, 0);
    mm_h<<<dim3(DIM_/BN_, MH/128), 256, SMH>>>(
        ff + (size_t)MH*HID_, cw2, out + (size_t)MH*DIM_, h1 + (size_t)MH*DIM_,
        HID_, HID_, HID_, DIM_, 2);
    // join s1 back into the mainline so the graph's leaf is on stream 0
    cudaStreamWaitEvent(0, eOut, 0);
}